// round 15
// baseline (speedup 1.0000x reference)
#include <cuda_runtime.h>
#include <cuda_bf16.h>
#include <cstdint>

// MatrixExpander: out(16,16,512,512) = kron(A(16,16,64,64), ones(8,8)), fp32.
//
// FINAL (R7): bench 43.49 / 43.49 / 43.52 / 44.42 us across 4 replays of
// this exact source (bench noise ~ +-0.9us); kernel 39.7-40.8us
// = 6.6-6.75 TB/s effective write, at the path-independent SM->LTS
// write-ingress cap (~6300 B/cyc, LDG.cv == TMA). 268 MB of output must
// cross LTS exactly once -> this is the chip roofline for the problem.
//
// Design: one CTA per tile. Tile c in [0,16384) covers out[c*4096 .. +4096)
// (16 KB contiguous) = 8 copies of the 512-float expanded row of A-row c,
// expanded[j] = A[c*64 + j/8]. Build the 16 KB tile in smem with a
// conflict-free fill, push with ONE cp.async.bulk store. The one-shot CTA
// swarm is the pipelining mechanism: the scheduler overlaps new CTAs' fills
// against in-flight bulk stores of retiring CTAs.
//
// Dead alternatives (R1-R14, all measured on-chip): plain STG 5.0 TB/s;
// STG/TMA hybrids <=6.2 (stcs-hybrid -15%); persistent double-buffered CTAs
// -10%; 2-tile / fewer-CTA variants -1.5%; 8x smem-source reuse = equal
// kernel, worse bench; stride-128B (conflicted) fill -45%; warp-autonomous
// 8x2KB stores = equal kernel, slightly worse bench.
//
// Fill layout: thread t writes float4 slots {t, t+256, t+512, t+768}:
//   - 16 B lane stride -> fully coalesced, zero bank conflicts
//   - all four slots need the SAME A col (t & 127) >> 1 -> one scalar load
//     (adjacent-thread broadcast), one splat, 4 STS.128.

__device__ __forceinline__ uint32_t smem_u32(const void* p) {
    uint32_t a;
    asm("{ .reg .u64 t; cvta.to.shared.u64 t, %1; cvt.u32.u64 %0, t; }"
        : "=r"(a) : "l"(p));
    return a;
}

__global__ __launch_bounds__(256)
void expander_tma_kernel(const float* __restrict__ A, float* __restrict__ out)
{
    __shared__ __align__(128) float4 buf[1024];   // 16 KB = 8 output rows

    const uint32_t c = blockIdx.x;   // tile id in [0, 16384)
    const uint32_t t = threadIdx.x;  // [0, 256)

    // One A value per thread (pairs of adjacent threads share -> broadcast).
    const float v = __ldg(A + (c << 6) + ((t & 127u) >> 1));
    const float4 v4 = make_float4(v, v, v, v);

    buf[t        ] = v4;
    buf[t + 256u ] = v4;
    buf[t + 512u ] = v4;
    buf[t + 768u ] = v4;

    __syncthreads();

    if (t == 0) {
        // Order generic-proxy STS before async-proxy bulk read.
        asm volatile("fence.proxy.async.shared::cta;" ::: "memory");
        const uint32_t s = smem_u32(buf);
        const float* dst = out + ((size_t)c << 12);   // c * 16 KB
        asm volatile(
            "cp.async.bulk.global.shared::cta.bulk_group [%0], [%1], %2;"
            :: "l"(dst), "r"(s), "n"(16384) : "memory");
        asm volatile("cp.async.bulk.commit_group;" ::: "memory");
        asm volatile("cp.async.bulk.wait_group 0;" ::: "memory");
    }
}

extern "C" void kernel_launch(void* const* d_in, const int* in_sizes, int n_in,
                              void* d_out, int out_size)
{
    const float* A = (const float*)d_in[0];   // (16,16,64,64) fp32
    float* out = (float*)d_out;               // (16,16,512,512) fp32

    // 16384 tiles x 16 KB = 256 MiB output
    expander_tma_kernel<<<16384, 256>>>(A, out);
}

// round 16
// speedup vs baseline: 1.0146x; 1.0146x over previous
#include <cuda_runtime.h>
#include <cuda_bf16.h>
#include <cstdint>

// MatrixExpander: out(16,16,512,512) = kron(A(16,16,64,64), ones(8,8)), fp32.
//
// FINAL (R7 champion): bench 43.49 / 43.49 / 43.52 / 44.42 / 44.42 us over
// five replays of this exact source (noise ~ +-0.9us; bench-kernel gap
// ~3.8us is fixed harness overhead). Kernel 39.7-40.8us = 6.6-6.75 TB/s
// effective write, at the path-independent SM->LTS write-ingress cap
// (~6300 B/cyc, LDG.cv == TMA). 268 MB of output must cross LTS exactly
// once -> this is the chip roofline for the problem.
//
// Design: one CTA per tile. Tile c in [0,16384) covers out[c*4096 .. +4096)
// (16 KB contiguous) = 8 copies of the 512-float expanded row of A-row c,
// expanded[j] = A[c*64 + j/8]. Build the 16 KB tile in smem with a
// conflict-free fill, push with ONE cp.async.bulk store. The one-shot CTA
// swarm is the pipelining mechanism: the scheduler overlaps new CTAs' fills
// against in-flight bulk stores of retiring CTAs.
//
// Dead alternatives (R1-R15, all measured on-chip): plain STG 5.0 TB/s;
// STG/TMA hybrids <=6.2 (stcs-hybrid -15%); persistent double-buffered CTAs
// -10%; 2-tile / fewer-CTA variants -1.5%; 8x smem-source reuse = equal
// kernel, worse bench; stride-128B (conflicted) fill -45%; warp-autonomous
// 8x2KB stores = equal kernel, slightly worse bench.
//
// Fill layout: thread t writes float4 slots {t, t+256, t+512, t+768}:
//   - 16 B lane stride -> fully coalesced, zero bank conflicts
//   - all four slots need the SAME A col (t & 127) >> 1 -> one scalar load
//     (adjacent-thread broadcast), one splat, 4 STS.128.

__device__ __forceinline__ uint32_t smem_u32(const void* p) {
    uint32_t a;
    asm("{ .reg .u64 t; cvta.to.shared.u64 t, %1; cvt.u32.u64 %0, t; }"
        : "=r"(a) : "l"(p));
    return a;
}

__global__ __launch_bounds__(256)
void expander_tma_kernel(const float* __restrict__ A, float* __restrict__ out)
{
    __shared__ __align__(128) float4 buf[1024];   // 16 KB = 8 output rows

    const uint32_t c = blockIdx.x;   // tile id in [0, 16384)
    const uint32_t t = threadIdx.x;  // [0, 256)

    // One A value per thread (pairs of adjacent threads share -> broadcast).
    const float v = __ldg(A + (c << 6) + ((t & 127u) >> 1));
    const float4 v4 = make_float4(v, v, v, v);

    buf[t        ] = v4;
    buf[t + 256u ] = v4;
    buf[t + 512u ] = v4;
    buf[t + 768u ] = v4;

    __syncthreads();

    if (t == 0) {
        // Order generic-proxy STS before async-proxy bulk read.
        asm volatile("fence.proxy.async.shared::cta;" ::: "memory");
        const uint32_t s = smem_u32(buf);
        const float* dst = out + ((size_t)c << 12);   // c * 16 KB
        asm volatile(
            "cp.async.bulk.global.shared::cta.bulk_group [%0], [%1], %2;"
            :: "l"(dst), "r"(s), "n"(16384) : "memory");
        asm volatile("cp.async.bulk.commit_group;" ::: "memory");
        asm volatile("cp.async.bulk.wait_group 0;" ::: "memory");
    }
}

extern "C" void kernel_launch(void* const* d_in, const int* in_sizes, int n_in,
                              void* d_out, int out_size)
{
    const float* A = (const float*)d_in[0];   // (16,16,64,64) fp32
    float* out = (float*)d_out;               // (16,16,512,512) fp32

    // 16384 tiles x 16 KB = 256 MiB output
    expander_tma_kernel<<<16384, 256>>>(A, out);
}

// round 17
// speedup vs baseline: 1.0213x; 1.0066x over previous
#include <cuda_runtime.h>
#include <cuda_bf16.h>
#include <cstdint>

// MatrixExpander: out(16,16,512,512) = kron(A(16,16,64,64), ones(8,8)), fp32.
//
// FINAL (R7 champion): bench 43.49 / 43.49 / 43.52 / 44.42 / 44.42 / 43.78 us
// over six replays of this exact source (noise ~ +-0.9us; bench-kernel gap
// ~3.8us is fixed harness overhead). Kernel 39.7-40.8us = 6.6-6.75 TB/s
// effective write, at the path-independent SM->LTS write-ingress cap
// (~6300 B/cyc, LDG.cv == TMA). 268 MB of output must cross LTS exactly
// once -> this is the chip roofline for the problem.
//
// Design: one CTA per tile. Tile c in [0,16384) covers out[c*4096 .. +4096)
// (16 KB contiguous) = 8 copies of the 512-float expanded row of A-row c,
// expanded[j] = A[c*64 + j/8]. Build the 16 KB tile in smem with a
// conflict-free fill, push with ONE cp.async.bulk store. The one-shot CTA
// swarm is the pipelining mechanism: the scheduler overlaps new CTAs' fills
// against in-flight bulk stores of retiring CTAs.
//
// Dead alternatives (R1-R16, all measured on-chip): plain STG 5.0 TB/s;
// STG/TMA hybrids <=6.2 (stcs-hybrid -15%); persistent double-buffered CTAs
// -10%; 2-tile / fewer-CTA variants -1.5%; 8x smem-source reuse = equal
// kernel, worse bench; stride-128B (conflicted) fill -45%; warp-autonomous
// 8x2KB stores = equal kernel, slightly worse bench.
//
// Fill layout: thread t writes float4 slots {t, t+256, t+512, t+768}:
//   - 16 B lane stride -> fully coalesced, zero bank conflicts
//   - all four slots need the SAME A col (t & 127) >> 1 -> one scalar load
//     (adjacent-thread broadcast), one splat, 4 STS.128.

__device__ __forceinline__ uint32_t smem_u32(const void* p) {
    uint32_t a;
    asm("{ .reg .u64 t; cvta.to.shared.u64 t, %1; cvt.u32.u64 %0, t; }"
        : "=r"(a) : "l"(p));
    return a;
}

__global__ __launch_bounds__(256)
void expander_tma_kernel(const float* __restrict__ A, float* __restrict__ out)
{
    __shared__ __align__(128) float4 buf[1024];   // 16 KB = 8 output rows

    const uint32_t c = blockIdx.x;   // tile id in [0, 16384)
    const uint32_t t = threadIdx.x;  // [0, 256)

    // One A value per thread (pairs of adjacent threads share -> broadcast).
    const float v = __ldg(A + (c << 6) + ((t & 127u) >> 1));
    const float4 v4 = make_float4(v, v, v, v);

    buf[t        ] = v4;
    buf[t + 256u ] = v4;
    buf[t + 512u ] = v4;
    buf[t + 768u ] = v4;

    __syncthreads();

    if (t == 0) {
        // Order generic-proxy STS before async-proxy bulk read.
        asm volatile("fence.proxy.async.shared::cta;" ::: "memory");
        const uint32_t s = smem_u32(buf);
        const float* dst = out + ((size_t)c << 12);   // c * 16 KB
        asm volatile(
            "cp.async.bulk.global.shared::cta.bulk_group [%0], [%1], %2;"
            :: "l"(dst), "r"(s), "n"(16384) : "memory");
        asm volatile("cp.async.bulk.commit_group;" ::: "memory");
        asm volatile("cp.async.bulk.wait_group 0;" ::: "memory");
    }
}

extern "C" void kernel_launch(void* const* d_in, const int* in_sizes, int n_in,
                              void* d_out, int out_size)
{
    const float* A = (const float*)d_in[0];   // (16,16,64,64) fp32
    float* out = (float*)d_out;               // (16,16,512,512) fp32

    // 16384 tiles x 16 KB = 256 MiB output
    expander_tma_kernel<<<16384, 256>>>(A, out);
}